// round 9
// baseline (speedup 1.0000x reference)
#include <cuda_runtime.h>
#include <cuda_bf16.h>
#include <cstdint>

typedef uint32_t u32; typedef uint64_t u64;

#define NB 128
#define NT 512
#define SS 512
#define HH 1024
#define NCHK 32
#define STG_A 16384
#define STG_B 4096
#define STG_STRIDE (2 * STG_A + 2 * STG_B)   // 40960
#define SMEM_DYN (2 * STG_STRIDE)            // 81920

// ---------- persistent device state ----------
__device__ __nv_bfloat16 g_W0h[8388608], g_W0l[8388608];   // [n'=j*4+g][k] (k contig, 2048)
__device__ __nv_bfloat16 g_W1h[8388608], g_W1l[8388608];
__device__ __nv_bfloat16 g_h0h[2][131072], g_h0l[2][131072];
__device__ __nv_bfloat16 g_h1h[2][131072], g_h1l[2][131072];
__device__ float g_sp[128][128];   // [b][cb]
__device__ unsigned g_cnt, g_gen;

// ---------- helpers ----------
__device__ __forceinline__ u32 smem_u32(const void* p) {
    u32 a; asm("{ .reg .u64 t; cvta.to.shared.u64 t, %1; cvt.u32.u64 %0, t; }" : "=r"(a) : "l"(p));
    return a;
}
__device__ __forceinline__ void ldsm4(u32 a, u32& r0, u32& r1, u32& r2, u32& r3) {
    asm volatile("ldmatrix.sync.aligned.m8n8.x4.shared.b16 {%0,%1,%2,%3}, [%4];"
        : "=r"(r0), "=r"(r1), "=r"(r2), "=r"(r3) : "r"(a));
}
__device__ __forceinline__ void mma16816(float* c, const u32* a, u32 b0, u32 b1) {
    asm volatile("mma.sync.aligned.m16n8k16.row.col.f32.bf16.bf16.f32 "
        "{%0,%1,%2,%3}, {%4,%5,%6,%7}, {%8,%9}, {%0,%1,%2,%3};"
        : "+f"(c[0]), "+f"(c[1]), "+f"(c[2]), "+f"(c[3])
        : "r"(a[0]), "r"(a[1]), "r"(a[2]), "r"(a[3]), "r"(b0), "r"(b1));
}
__device__ __forceinline__ u32 pkbf2(float f0, float f1) {  // mem order [f0,f1]
    u32 r; asm("cvt.rn.bf16x2.f32 %0, %1, %2;" : "=r"(r) : "f"(f1), "f"(f0)); return r;
}
__device__ __forceinline__ void cvt8(uint4& hi, uint4& lo, float4 a, float4 b) {
    hi.x = pkbf2(a.x, a.y); hi.y = pkbf2(a.z, a.w);
    hi.z = pkbf2(b.x, b.y); hi.w = pkbf2(b.z, b.w);
    lo.x = pkbf2(a.x - __uint_as_float(hi.x << 16), a.y - __uint_as_float(hi.x & 0xffff0000u));
    lo.y = pkbf2(a.z - __uint_as_float(hi.y << 16), a.w - __uint_as_float(hi.y & 0xffff0000u));
    lo.z = pkbf2(b.x - __uint_as_float(hi.z << 16), b.y - __uint_as_float(hi.z & 0xffff0000u));
    lo.w = pkbf2(b.z - __uint_as_float(hi.w << 16), b.w - __uint_as_float(hi.w & 0xffff0000u));
}
__device__ __forceinline__ void sts16(char* base, int off, uint4 v) {
    *(uint4*)(base + (off ^ ((off >> 3) & 0x70))) = v;
}
__device__ __forceinline__ void sts8(char* base, int off, uint2 v) {
    *(uint2*)(base + (off ^ ((off >> 3) & 0x70))) = v;
}

// ---------- init kernels ----------
__global__ void init_kernel() {
    int i = blockIdx.x * blockDim.x + threadIdx.x;
    __nv_bfloat16 z = __float2bfloat16(0.f);
    if (i < 131072) { g_h0h[0][i] = z; g_h0l[0][i] = z; g_h1h[0][i] = z; g_h1l[0][i] = z; }
    if (i == 0) { g_cnt = 0; g_gen = 0; }
}
__global__ void conv_w(const float* __restrict__ U0, const float* __restrict__ V0,
                       const float* __restrict__ U1, const float* __restrict__ V1) {
    size_t i = (size_t)blockIdx.x * 256 + threadIdx.x;   // 2 * 4096 * 2048
    int layer = (int)(i >> 23);
    size_t r = i & 8388607;
    int np = (int)(r >> 11), k = (int)(r & 2047);
    int g = np & 3, j = np >> 2;
    const float* src = layer ? (k < 1024 ? U1 : V1) : (k < 1024 ? U0 : V0);
    float v = src[(size_t)(k & 1023) * 4096 + g * 1024 + j];
    __nv_bfloat16 hi = __float2bfloat16(v);
    __nv_bfloat16 lo = __float2bfloat16(v - __bfloat162float(hi));
    if (layer) { g_W1h[r] = hi; g_W1l[r] = lo; }
    else       { g_W0h[r] = hi; g_W0l[r] = lo; }
}

// ---------- grid barrier ----------
__device__ __forceinline__ void gbar(unsigned target) {
    __syncthreads();
    if (threadIdx.x == 0) {
        __threadfence();
        if (atomicAdd(&g_cnt, 1u) == NB - 1) {
            g_cnt = 0; __threadfence(); atomicAdd(&g_gen, 1u);
        } else {
            while (*(volatile unsigned*)&g_gen < target) {}
        }
        __threadfence();
    }
    __syncthreads();
}

// ---------- staged fragment load (NT=512 threads) ----------
struct Frag { uint4 ah[2], al[2]; uint2 bh, bl; };

template <int CELL>
__device__ __forceinline__ void load_frag(Frag& f, int ch, int t, int p, int n0, int tid,
                                          const float* __restrict__ x) {
    const int k0 = ch * 64;
    {
        const __nv_bfloat16* Wh = CELL ? g_W1h : g_W0h;
        const __nv_bfloat16* Wl = CELL ? g_W1l : g_W0l;
        size_t wo = (size_t)(n0 + (tid >> 4)) * 2048 + k0 + (tid & 15) * 4;
        f.bh = __ldg((const uint2*)(Wh + wo));
        f.bl = __ldg((const uint2*)(Wl + wo));
    }
    if (CELL == 0 && ch < 16) {
#pragma unroll
        for (int it = 0; it < 2; it++) {
            int slot = it * NT + tid;
            int b = slot >> 3, k = k0 + (slot & 7) * 8;
            const float* src = x + ((size_t)b * SS + t) * HH + k;
            float4 v0 = __ldg((const float4*)src);
            float4 v1 = __ldg((const float4*)(src + 4));
            cvt8(f.ah[it], f.al[it], v0, v1);
        }
    } else {
        const __nv_bfloat16 *sh, *sl;
        if (CELL == 0)      { sh = g_h0h[p];     sl = g_h0l[p]; }
        else if (ch < 16)   { sh = g_h0h[1 - p]; sl = g_h0l[1 - p]; }
        else                { sh = g_h1h[p];     sl = g_h1l[p]; }
        int kb = k0 & 1023;
#pragma unroll
        for (int it = 0; it < 2; it++) {
            int slot = it * NT + tid;
            int b = slot >> 3, k = kb + (slot & 7) * 8;
            size_t o = (size_t)b * HH + k;
            f.ah[it] = __ldcg((const uint4*)(sh + o));
            f.al[it] = __ldcg((const uint4*)(sl + o));
        }
    }
}

__device__ __forceinline__ void sts_frag(char* stage, const Frag& f, int tid) {
    int off = (tid >> 4) * 128 + (tid & 15) * 8;
    sts8(stage + 2 * STG_A, off, f.bh);
    sts8(stage + 2 * STG_A + STG_B, off, f.bl);
#pragma unroll
    for (int it = 0; it < 2; it++) {
        int slot = it * NT + tid;
        int o2 = (slot >> 3) * 128 + (slot & 7) * 16;
        sts16(stage, o2, f.ah[it]);
        sts16(stage + STG_A, o2, f.al[it]);
    }
}

struct SmemT {
    float As[32][129];
    float bias[2][32];
    float sw8[8];
};

// ---------- GEMM: warp w -> rows 16*(w&7)..+15, cols 16*(w>>3)..+15 ----------
template <int CELL>
__device__ __forceinline__ void run_gemm(SmemT& s, char* dyn, const float* __restrict__ x,
    int t, int p, int n0, int tid, float acc[2][4], u32 dynb)
{
    const int lane = tid & 31, w = tid >> 5;
    const int rw = w & 7, cw = w >> 3;
    const int arow = 16 * rw + (lane & 15);
    const int akhi = lane >> 4;
    const int brow = (lane & 7) + ((lane >> 4) << 3);
    const int bkhi = (lane >> 3) & 1;
    const u32 aoff = (u32)arow * 128;
    const int asw = arow & 7;
    const u32 boff = (u32)(cw * 16 + brow) * 128;
    const int bsw = brow & 7;

    Frag f;
    load_frag<CELL>(f, 0, t, p, n0, tid, x);
    sts_frag(dyn, f, tid);
    load_frag<CELL>(f, 1, t, p, n0, tid, x);
    __syncthreads();

#pragma unroll 1
    for (int ch = 0; ch < NCHK; ch++) {
        if (ch + 1 < NCHK) sts_frag(dyn + ((ch + 1) & 1) * STG_STRIDE, f, tid);
        if (ch + 2 < NCHK) load_frag<CELL>(f, ch + 2, t, p, n0, tid, x);
        const u32 base = dynb + (u32)((ch & 1) * STG_STRIDE);
        const u32 aAh = base + aoff;
        const u32 aAl = base + STG_A + aoff;
        const u32 aBh = base + 2 * STG_A + boff;
        const u32 aBl = base + 2 * STG_A + STG_B + boff;
#pragma unroll
        for (int ks = 0; ks < 4; ks++) {
            const u32 ao = (u32)(((2 * ks + akhi) ^ asw) << 4);
            const u32 bo = (u32)(((2 * ks + bkhi) ^ bsw) << 4);
            u32 ah[4], al[4], bh[4], bl[4];
            ldsm4(aAh + ao, ah[0], ah[1], ah[2], ah[3]);
            ldsm4(aAl + ao, al[0], al[1], al[2], al[3]);
            ldsm4(aBh + bo, bh[0], bh[1], bh[2], bh[3]);
            ldsm4(aBl + bo, bl[0], bl[1], bl[2], bl[3]);
            mma16816(acc[0], ah, bh[0], bh[1]);
            mma16816(acc[1], ah, bh[2], bh[3]);
            mma16816(acc[0], ah, bl[0], bl[1]);
            mma16816(acc[1], ah, bl[2], bl[3]);
            mma16816(acc[0], al, bh[0], bh[1]);
            mma16816(acc[1], al, bh[2], bh[3]);
        }
        __syncthreads();
    }
    // park acc in As
#pragma unroll
    for (int fr = 0; fr < 2; fr++) {
        int nn = cw * 16 + fr * 8 + 2 * (lane & 3);
        int r = 16 * rw + (lane >> 2);
        s.As[nn][r]         = acc[fr][0];
        s.As[nn + 1][r]     = acc[fr][1];
        s.As[nn][r + 8]     = acc[fr][2];
        s.As[nn + 1][r + 8] = acc[fr][3];
    }
    __syncthreads();
}

// ---------- main persistent kernel ----------
__global__ void __launch_bounds__(NT, 1) lstm_kernel(
    const float* __restrict__ x,
    const float* __restrict__ b0, const float* __restrict__ b1,
    const float* __restrict__ sw, const float* __restrict__ sb,
    float* __restrict__ out) {
    extern __shared__ __align__(1024) char dyn[];
    __shared__ SmemT s;

    const int tid = threadIdx.x, cb = blockIdx.x;
    const int j0 = cb * 8, n0 = cb * 32;

    if (tid < 64) {
        int layer = tid >> 5, c = tid & 31;
        const float* bp = layer ? b1 : b0;
        s.bias[layer][c] = bp[(c & 3) * 1024 + j0 + (c >> 2)];
    }
    if (tid < 8) s.sw8[tid] = sw[j0 + tid];
    __syncthreads();

    const u32 dynb = smem_u32(dyn);

    float c0r[8] = {}, c1r[8] = {}, h0r[8] = {}, h1r[8] = {};
    float ut = 1.f;
    unsigned bt = 0;

#pragma unroll 1
    for (int t = 0; t < SS; t++) {
        const int p = t & 1;
        // ===== layer 0 =====
        {
            float acc[2][4] = {};
            run_gemm<0>(s, dyn, x, t, p, n0, tid, acc, dynb);
        }
        if (tid < 128) {
            int b = tid;
            float u = rintf(ut);
#pragma unroll
            for (int jj = 0; jj < 8; jj++) {
                float ai = s.As[jj * 4 + 0][b] + s.bias[0][jj * 4 + 0];
                float af = s.As[jj * 4 + 1][b] + s.bias[0][jj * 4 + 1];
                float ag = s.As[jj * 4 + 2][b] + s.bias[0][jj * 4 + 2];
                float ao = s.As[jj * 4 + 3][b] + s.bias[0][jj * 4 + 3];
                float ig = 1.f / (1.f + expf(-ai));
                float fg = 1.f / (1.f + expf(-af));
                float gg = tanhf(ag);
                float og = 1.f / (1.f + expf(-ao));
                float cn = fg * c0r[jj] + ig * gg;
                c0r[jj] = cn;
                float hn = u * (og * tanhf(cn)) + (1.f - u) * h0r[jj];
                h0r[jj] = hn;
                __nv_bfloat16 hi = __float2bfloat16(hn);
                __stcg(&g_h0h[1 - p][(size_t)b * HH + j0 + jj], hi);
                __stcg(&g_h0l[1 - p][(size_t)b * HH + j0 + jj],
                       __float2bfloat16(hn - __bfloat162float(hi)));
            }
        }
        gbar(++bt);
        // ===== layer 1 =====
        {
            float acc[2][4] = {};
            run_gemm<1>(s, dyn, x, t, p, n0, tid, acc, dynb);
        }
        if (tid < 128) {
            int b = tid;
            float u = rintf(ut);
            float sp = 0.f;
#pragma unroll
            for (int jj = 0; jj < 8; jj++) {
                float ai = s.As[jj * 4 + 0][b] + s.bias[1][jj * 4 + 0];
                float af = s.As[jj * 4 + 1][b] + s.bias[1][jj * 4 + 1];
                float ag = s.As[jj * 4 + 2][b] + s.bias[1][jj * 4 + 2];
                float ao = s.As[jj * 4 + 3][b] + s.bias[1][jj * 4 + 3];
                float ig = 1.f / (1.f + expf(-ai));
                float fg = 1.f / (1.f + expf(-af));
                float gg = tanhf(ag);
                float og = 1.f / (1.f + expf(-ao));
                float cn = fg * c1r[jj] + ig * gg;
                c1r[jj] = cn;
                sp += cn * s.sw8[jj];
                float hn = u * (og * tanhf(cn)) + (1.f - u) * h1r[jj];
                h1r[jj] = hn;
                __nv_bfloat16 hi = __float2bfloat16(hn);
                __stcg(&g_h1h[1 - p][(size_t)b * HH + j0 + jj], hi);
                __stcg(&g_h1l[1 - p][(size_t)b * HH + j0 + jj],
                       __float2bfloat16(hn - __bfloat162float(hi)));
                out[((size_t)b * SS + t) * HH + j0 + jj] = hn;
            }
            __stcg(&g_sp[b][cb], sp);
        }
        gbar(++bt);
        if (tid < 128) {
            float tot = sb[0];
            const float4* q = (const float4*)&g_sp[tid][0];
#pragma unroll
            for (int i = 0; i < 32; i++) {
                float4 v = __ldcg(q + i);
                tot += v.x + v.y + v.z + v.w;
            }
            float cum = 1.f / (1.f + expf(-tot));
            float u = rintf(ut);
            ut = (u > 0.5f) ? cum : (ut + fminf(cum, 1.f - ut));
        }
        __syncthreads();
    }
}

extern "C" void kernel_launch(void* const* d_in, const int* in_sizes, int n_in,
                              void* d_out, int out_size) {
    (void)in_sizes; (void)n_in; (void)out_size;
    const float* x  = (const float*)d_in[0];
    const float* U0 = (const float*)d_in[1];
    const float* V0 = (const float*)d_in[2];
    const float* b0 = (const float*)d_in[3];
    const float* U1 = (const float*)d_in[4];
    const float* V1 = (const float*)d_in[5];
    const float* b1 = (const float*)d_in[6];
    const float* sw = (const float*)d_in[7];
    const float* sb = (const float*)d_in[8];
    float* out = (float*)d_out;

    cudaFuncSetAttribute(lstm_kernel, cudaFuncAttributeMaxDynamicSharedMemorySize, SMEM_DYN);
    init_kernel<<<512, 256>>>();
    conv_w<<<65536, 256>>>(U0, V0, U1, V1);
    lstm_kernel<<<NB, NT, SMEM_DYN>>>(x, b0, b1, sw, sb, out);
}

// round 10
// speedup vs baseline: 1.1179x; 1.1179x over previous
#include <cuda_runtime.h>
#include <cuda_bf16.h>
#include <cstdint>

typedef uint32_t u32; typedef uint64_t u64;

#define NB 128
#define SS 512
#define HH 1024
#define NCHK 32
#define STG_A 16384
#define STG_B 4096
#define STG_STRIDE (2 * STG_A + 2 * STG_B)   // 40960
#define SMEM_DYN (2 * STG_STRIDE)            // 81920

// ---------- persistent device state ----------
__device__ __nv_bfloat16 g_W0h[8388608], g_W0l[8388608];   // [n'=j*4+g][k] (k contig, 2048)
__device__ __nv_bfloat16 g_W1h[8388608], g_W1l[8388608];
__device__ __nv_bfloat16 g_h0h[2][131072], g_h0l[2][131072];
__device__ __nv_bfloat16 g_h1h[2][131072], g_h1l[2][131072];
__device__ float g_sp[128][128];   // [b][cb]
__device__ unsigned g_cnt, g_gen;

// ---------- helpers ----------
__device__ __forceinline__ u32 smem_u32(const void* p) {
    u32 a; asm("{ .reg .u64 t; cvta.to.shared.u64 t, %1; cvt.u32.u64 %0, t; }" : "=r"(a) : "l"(p));
    return a;
}
__device__ __forceinline__ void ldsm4(u32 a, u32& r0, u32& r1, u32& r2, u32& r3) {
    asm volatile("ldmatrix.sync.aligned.m8n8.x4.shared.b16 {%0,%1,%2,%3}, [%4];"
        : "=r"(r0), "=r"(r1), "=r"(r2), "=r"(r3) : "r"(a));
}
__device__ __forceinline__ void mma16816(float* c, const u32* a, u32 b0, u32 b1) {
    asm volatile("mma.sync.aligned.m16n8k16.row.col.f32.bf16.bf16.f32 "
        "{%0,%1,%2,%3}, {%4,%5,%6,%7}, {%8,%9}, {%0,%1,%2,%3};"
        : "+f"(c[0]), "+f"(c[1]), "+f"(c[2]), "+f"(c[3])
        : "r"(a[0]), "r"(a[1]), "r"(a[2]), "r"(a[3]), "r"(b0), "r"(b1));
}
__device__ __forceinline__ u32 pkbf2(float f0, float f1) {  // mem order [f0,f1]
    u32 r; asm("cvt.rn.bf16x2.f32 %0, %1, %2;" : "=r"(r) : "f"(f1), "f"(f0)); return r;
}
__device__ __forceinline__ void cvt8(uint4& hi, uint4& lo, float4 a, float4 b) {
    hi.x = pkbf2(a.x, a.y); hi.y = pkbf2(a.z, a.w);
    hi.z = pkbf2(b.x, b.y); hi.w = pkbf2(b.z, b.w);
    lo.x = pkbf2(a.x - __uint_as_float(hi.x << 16), a.y - __uint_as_float(hi.x & 0xffff0000u));
    lo.y = pkbf2(a.z - __uint_as_float(hi.y << 16), a.w - __uint_as_float(hi.y & 0xffff0000u));
    lo.z = pkbf2(b.x - __uint_as_float(hi.z << 16), b.y - __uint_as_float(hi.z & 0xffff0000u));
    lo.w = pkbf2(b.z - __uint_as_float(hi.w << 16), b.w - __uint_as_float(hi.w & 0xffff0000u));
}
__device__ __forceinline__ void sts16(char* base, int off, uint4 v) {
    *(uint4*)(base + (off ^ ((off >> 3) & 0x70))) = v;
}
__device__ __forceinline__ float sigf(float x) {
    return __fdividef(1.f, 1.f + __expf(-x));
}
__device__ __forceinline__ float tanhfast(float x) {
    return 1.f - __fdividef(2.f, 1.f + __expf(2.f * x));
}

// ---------- init kernels ----------
__global__ void init_kernel() {
    int i = blockIdx.x * blockDim.x + threadIdx.x;
    __nv_bfloat16 z = __float2bfloat16(0.f);
    if (i < 131072) { g_h0h[0][i] = z; g_h0l[0][i] = z; g_h1h[0][i] = z; g_h1l[0][i] = z; }
    if (i == 0) { g_cnt = 0; g_gen = 0; }
}
__global__ void conv_w(const float* __restrict__ U0, const float* __restrict__ V0,
                       const float* __restrict__ U1, const float* __restrict__ V1) {
    size_t i = (size_t)blockIdx.x * 256 + threadIdx.x;   // 2 * 4096 * 2048
    int layer = (int)(i >> 23);
    size_t r = i & 8388607;
    int np = (int)(r >> 11), k = (int)(r & 2047);
    int g = np & 3, j = np >> 2;
    const float* src = layer ? (k < 1024 ? U1 : V1) : (k < 1024 ? U0 : V0);
    float v = src[(size_t)(k & 1023) * 4096 + g * 1024 + j];
    __nv_bfloat16 hi = __float2bfloat16(v);
    __nv_bfloat16 lo = __float2bfloat16(v - __bfloat162float(hi));
    if (layer) { g_W1h[r] = hi; g_W1l[r] = lo; }
    else       { g_W0h[r] = hi; g_W0l[r] = lo; }
}

// ---------- split grid barrier ----------
__device__ __forceinline__ void gbar_arrive() {
    __syncthreads();
    if (threadIdx.x == 0) {
        __threadfence();
        if (atomicAdd(&g_cnt, 1u) == NB - 1) {
            g_cnt = 0; __threadfence(); atomicAdd(&g_gen, 1u);
        }
    }
}
__device__ __forceinline__ void gbar_wait(unsigned target) {
    if (threadIdx.x == 0) {
        while (*(volatile unsigned*)&g_gen < target) {}
        __threadfence();
    }
    __syncthreads();
}

// ---------- staged fragment load (256 threads) ----------
struct Frag { uint4 ah[4], al[4], bh, bl; };

template <int CELL>
__device__ __forceinline__ void load_frag(Frag& f, int ch, int t, int p, int n0, int tid,
                                          const float* __restrict__ x) {
    const int k0 = ch * 64;
    {
        const __nv_bfloat16* Wh = CELL ? g_W1h : g_W0h;
        const __nv_bfloat16* Wl = CELL ? g_W1l : g_W0l;
        size_t wo = (size_t)(n0 + (tid >> 3)) * 2048 + k0 + (tid & 7) * 8;
        f.bh = __ldg((const uint4*)(Wh + wo));
        f.bl = __ldg((const uint4*)(Wl + wo));
    }
    if (CELL == 0 && ch < 16) {
#pragma unroll
        for (int it = 0; it < 4; it++) {
            int slot = it * 256 + tid;
            int b = slot >> 3, k = k0 + (slot & 7) * 8;
            const float* src = x + ((size_t)b * SS + t) * HH + k;
            float4 v0 = __ldg((const float4*)src);
            float4 v1 = __ldg((const float4*)(src + 4));
            cvt8(f.ah[it], f.al[it], v0, v1);
        }
    } else {
        const __nv_bfloat16 *sh, *sl;
        if (CELL == 0)      { sh = g_h0h[p];     sl = g_h0l[p]; }
        else if (ch < 16)   { sh = g_h0h[1 - p]; sl = g_h0l[1 - p]; }
        else                { sh = g_h1h[p];     sl = g_h1l[p]; }
        int kb = k0 & 1023;
#pragma unroll
        for (int it = 0; it < 4; it++) {
            int slot = it * 256 + tid;
            int b = slot >> 3, k = kb + (slot & 7) * 8;
            size_t o = (size_t)b * HH + k;
            f.ah[it] = __ldcg((const uint4*)(sh + o));
            f.al[it] = __ldcg((const uint4*)(sl + o));
        }
    }
}

__device__ __forceinline__ void sts_frag(char* stage, const Frag& f, int tid) {
    int off = (tid >> 3) * 128 + (tid & 7) * 16;
    sts16(stage + 2 * STG_A, off, f.bh);
    sts16(stage + 2 * STG_A + STG_B, off, f.bl);
#pragma unroll
    for (int it = 0; it < 4; it++) {
        int slot = it * 256 + tid;
        int o2 = (slot >> 3) * 128 + (slot & 7) * 16;
        sts16(stage, o2, f.ah[it]);
        sts16(stage + STG_A, o2, f.al[it]);
    }
}

struct SmemT {
    float As[32][129];
    float bias[2][32];
    float sw8[8];
};

// ---------- GEMM: warp w -> rows 16w..16w+15, cols 0..31; ks-pipelined ----------
template <int CELL>
__device__ __forceinline__ void run_gemm(SmemT& s, char* dyn, const float* __restrict__ x,
    int t, int p, int n0, int tid, float acc[4][4], u32 dynb, unsigned waitTarget)
{
    const int lane = tid & 31, w = tid >> 5;
    const int arow = 16 * w + (lane & 15);
    const int akhi = lane >> 4;
    const int brow = (lane & 7) + ((lane >> 4) << 3);
    const int bkhi = (lane >> 3) & 1;
    const u32 aoff = (u32)arow * 128;
    const int asw = arow & 7;
    const u32 boff = (u32)brow * 128;
    const int bsw = brow & 7;

    Frag f;
    load_frag<CELL>(f, CELL ? 16 : 0, t, p, n0, tid, x);
    sts_frag(dyn, f, tid);
    load_frag<CELL>(f, CELL ? 17 : 1, t, p, n0, tid, x);
    __syncthreads();

#pragma unroll 1
    for (int it = 0; it < NCHK; it++) {
        if (it + 1 < NCHK) sts_frag(dyn + ((it + 1) & 1) * STG_STRIDE, f, tid);
        if (CELL == 1 && it == 14) gbar_wait(waitTarget);   // h0-dependent chunks start at it=16
        if (it + 2 < NCHK) {
            int ch = CELL ? ((it + 18) & 31) : (it + 2);
            load_frag<CELL>(f, ch, t, p, n0, tid, x);
        }
        const u32 base = dynb + (u32)((it & 1) * STG_STRIDE);
        const u32 aAh = base + aoff;
        const u32 aAl = base + STG_A + aoff;
        const u32 aBh = base + 2 * STG_A + boff;
        const u32 aBl = base + 2 * STG_A + STG_B + boff;

        u32 ah[2][4], al[2][4], bh[2][8], bl[2][8];
        {
            const u32 ao = (u32)((akhi ^ asw) << 4);
            const u32 bo = (u32)((bkhi ^ bsw) << 4);
            ldsm4(aAh + ao, ah[0][0], ah[0][1], ah[0][2], ah[0][3]);
            ldsm4(aAl + ao, al[0][0], al[0][1], al[0][2], al[0][3]);
            ldsm4(aBh + bo, bh[0][0], bh[0][1], bh[0][2], bh[0][3]);
            ldsm4(aBh + 16 * 128 + bo, bh[0][4], bh[0][5], bh[0][6], bh[0][7]);
            ldsm4(aBl + bo, bl[0][0], bl[0][1], bl[0][2], bl[0][3]);
            ldsm4(aBl + 16 * 128 + bo, bl[0][4], bl[0][5], bl[0][6], bl[0][7]);
        }
#pragma unroll
        for (int ks = 0; ks < 4; ks++) {
            const int cu = ks & 1, nx = cu ^ 1;
            if (ks < 3) {
                const u32 ao = (u32)(((2 * (ks + 1) + akhi) ^ asw) << 4);
                const u32 bo = (u32)(((2 * (ks + 1) + bkhi) ^ bsw) << 4);
                ldsm4(aAh + ao, ah[nx][0], ah[nx][1], ah[nx][2], ah[nx][3]);
                ldsm4(aAl + ao, al[nx][0], al[nx][1], al[nx][2], al[nx][3]);
                ldsm4(aBh + bo, bh[nx][0], bh[nx][1], bh[nx][2], bh[nx][3]);
                ldsm4(aBh + 16 * 128 + bo, bh[nx][4], bh[nx][5], bh[nx][6], bh[nx][7]);
                ldsm4(aBl + bo, bl[nx][0], bl[nx][1], bl[nx][2], bl[nx][3]);
                ldsm4(aBl + 16 * 128 + bo, bl[nx][4], bl[nx][5], bl[nx][6], bl[nx][7]);
            }
            mma16816(acc[0], ah[cu], bh[cu][0], bh[cu][1]);
            mma16816(acc[1], ah[cu], bh[cu][2], bh[cu][3]);
            mma16816(acc[2], ah[cu], bh[cu][4], bh[cu][5]);
            mma16816(acc[3], ah[cu], bh[cu][6], bh[cu][7]);
            mma16816(acc[0], ah[cu], bl[cu][0], bl[cu][1]);
            mma16816(acc[1], ah[cu], bl[cu][2], bl[cu][3]);
            mma16816(acc[2], ah[cu], bl[cu][4], bl[cu][5]);
            mma16816(acc[3], ah[cu], bl[cu][6], bl[cu][7]);
            mma16816(acc[0], al[cu], bh[cu][0], bh[cu][1]);
            mma16816(acc[1], al[cu], bh[cu][2], bh[cu][3]);
            mma16816(acc[2], al[cu], bh[cu][4], bh[cu][5]);
            mma16816(acc[3], al[cu], bh[cu][6], bh[cu][7]);
        }
        __syncthreads();
    }
#pragma unroll
    for (int fr = 0; fr < 4; fr++) {
        int nn = fr * 8 + 2 * (lane & 3);
        int r = 16 * w + (lane >> 2);
        s.As[nn][r]         = acc[fr][0];
        s.As[nn + 1][r]     = acc[fr][1];
        s.As[nn][r + 8]     = acc[fr][2];
        s.As[nn + 1][r + 8] = acc[fr][3];
    }
    __syncthreads();
}

// ---------- main persistent kernel ----------
__global__ void __launch_bounds__(256, 1) lstm_kernel(
    const float* __restrict__ x,
    const float* __restrict__ b0, const float* __restrict__ b1,
    const float* __restrict__ sw, const float* __restrict__ sb,
    float* __restrict__ out) {
    extern __shared__ __align__(1024) char dyn[];
    __shared__ SmemT s;

    const int tid = threadIdx.x, cb = blockIdx.x;
    const int j0 = cb * 8, n0 = cb * 32;

    if (tid < 64) {
        int layer = tid >> 5, c = tid & 31;
        const float* bp = layer ? b1 : b0;
        s.bias[layer][c] = bp[(c & 3) * 1024 + j0 + (c >> 2)];
    }
    if (tid < 8) s.sw8[tid] = sw[j0 + tid];
    __syncthreads();

    const u32 dynb = smem_u32(dyn);

    float c0r[8] = {}, c1r[8] = {}, h0r[8] = {}, h1r[8] = {};
    float ut = 1.f;
    unsigned bt = 0, wA = 0, wB = 0;

#pragma unroll 1
    for (int t = 0; t < SS; t++) {
        const int p = t & 1;
        // ===== layer 0 GEMM (needs no fresh barrier; h0[p] protected by earlier phases) =====
        {
            float acc[4][4] = {};
            run_gemm<0>(s, dyn, x, t, p, n0, tid, acc, dynb, 0u);
        }
        // ===== deferred skip-gate update for step t-1 (barrier B hidden under L0 GEMM) =====
        if (t > 0) {
            gbar_wait(wB);
            if (tid < 128) {
                float tot = sb[0];
                const float4* q = (const float4*)&g_sp[tid][0];
#pragma unroll
                for (int i = 0; i < 32; i++) {
                    float4 v = __ldcg(q + i);
                    tot += v.x + v.y + v.z + v.w;
                }
                float cum = sigf(tot);
                float u = rintf(ut);
                ut = (u > 0.5f) ? cum : (ut + fminf(cum, 1.f - ut));
            }
        }
        // ===== layer 0 epilogue =====
        if (tid < 128) {
            int b = tid;
            float u = rintf(ut);
#pragma unroll
            for (int jj = 0; jj < 8; jj++) {
                float ai = s.As[jj * 4 + 0][b] + s.bias[0][jj * 4 + 0];
                float af = s.As[jj * 4 + 1][b] + s.bias[0][jj * 4 + 1];
                float ag = s.As[jj * 4 + 2][b] + s.bias[0][jj * 4 + 2];
                float ao = s.As[jj * 4 + 3][b] + s.bias[0][jj * 4 + 3];
                float ig = sigf(ai);
                float fg = sigf(af);
                float gg = tanhfast(ag);
                float og = sigf(ao);
                float cn = fg * c0r[jj] + ig * gg;
                c0r[jj] = cn;
                float hn = u * (og * tanhfast(cn)) + (1.f - u) * h0r[jj];
                h0r[jj] = hn;
                __nv_bfloat16 hi = __float2bfloat16(hn);
                __stcg(&g_h0h[1 - p][(size_t)b * HH + j0 + jj], hi);
                __stcg(&g_h0l[1 - p][(size_t)b * HH + j0 + jj],
                       __float2bfloat16(hn - __bfloat162float(hi)));
            }
        }
        gbar_arrive(); wA = ++bt;
        // ===== layer 1 GEMM (h1 chunks first; waits for barrier A at it==14) =====
        {
            float acc[4][4] = {};
            run_gemm<1>(s, dyn, x, t, p, n0, tid, acc, dynb, wA);
        }
        // ===== layer 1 epilogue =====
        if (tid < 128) {
            int b = tid;
            float u = rintf(ut);
            float sp = 0.f;
#pragma unroll
            for (int jj = 0; jj < 8; jj++) {
                float ai = s.As[jj * 4 + 0][b] + s.bias[1][jj * 4 + 0];
                float af = s.As[jj * 4 + 1][b] + s.bias[1][jj * 4 + 1];
                float ag = s.As[jj * 4 + 2][b] + s.bias[1][jj * 4 + 2];
                float ao = s.As[jj * 4 + 3][b] + s.bias[1][jj * 4 + 3];
                float ig = sigf(ai);
                float fg = sigf(af);
                float gg = tanhfast(ag);
                float og = sigf(ao);
                float cn = fg * c1r[jj] + ig * gg;
                c1r[jj] = cn;
                sp += cn * s.sw8[jj];
                float hn = u * (og * tanhfast(cn)) + (1.f - u) * h1r[jj];
                h1r[jj] = hn;
                __nv_bfloat16 hi = __float2bfloat16(hn);
                __stcg(&g_h1h[1 - p][(size_t)b * HH + j0 + jj], hi);
                __stcg(&g_h1l[1 - p][(size_t)b * HH + j0 + jj],
                       __float2bfloat16(hn - __bfloat162float(hi)));
                out[((size_t)b * SS + t) * HH + j0 + jj] = hn;
            }
            __stcg(&g_sp[b][cb], sp);
        }
        gbar_arrive(); wB = ++bt;
    }
}

extern "C" void kernel_launch(void* const* d_in, const int* in_sizes, int n_in,
                              void* d_out, int out_size) {
    (void)in_sizes; (void)n_in; (void)out_size;
    const float* x  = (const float*)d_in[0];
    const float* U0 = (const float*)d_in[1];
    const float* V0 = (const float*)d_in[2];
    const float* b0 = (const float*)d_in[3];
    const float* U1 = (const float*)d_in[4];
    const float* V1 = (const float*)d_in[5];
    const float* b1 = (const float*)d_in[6];
    const float* sw = (const float*)d_in[7];
    const float* sb = (const float*)d_in[8];
    float* out = (float*)d_out;

    cudaFuncSetAttribute(lstm_kernel, cudaFuncAttributeMaxDynamicSharedMemorySize, SMEM_DYN);
    init_kernel<<<512, 256>>>();
    conv_w<<<65536, 256>>>(U0, V0, U1, V1);
    lstm_kernel<<<NB, 256, SMEM_DYN>>>(x, b0, b1, sw, sb, out);
}